// round 1
// baseline (speedup 1.0000x reference)
#include <cuda_runtime.h>
#include <math.h>

#define BB 8
#define CC 64
#define OO 64
#define HH 128
#define WW 128
#define HWSZ (HH * WW)

// scratch for z = W @ x  (33.5 MB) — static device array (no allocations allowed)
__device__ float g_z[BB * OO * HWSZ];

// ---------------------------------------------------------------------------
// K1: z[b][o][hw] = sum_c core[o][c] * x[b][c][hw]
// Grid: (HWSZ/256, BB). Block: 256 threads. Each thread owns one position,
// accumulates all 64 output channels in registers.
// Dynamic smem: ws[64][64] (w transposed, [c][o]) + xs[64][256]  = 80 KB.
// ---------------------------------------------------------------------------
__global__ void spconv_gemm_kernel(const float* __restrict__ x,
                                   const float* __restrict__ core,
                                   float* __restrict__ z) {
    extern __shared__ float smem[];
    float* ws = smem;            // [c][o], 4096 floats
    float* xs = smem + 4096;     // [c][256], 16384 floats

    const int tid  = threadIdx.x;
    const int b    = blockIdx.y;
    const int base = blockIdx.x * 256;

    // load W transposed: ws[c*64 + o] = core[o*64 + c]
    for (int i = tid; i < 4096; i += 256) {
        int o = i >> 6;
        int c = i & 63;
        ws[c * 64 + o] = core[o * 64 + c];
    }
    const float* xb = x + (size_t)b * CC * HWSZ + base;
    for (int c = 0; c < CC; c++) {
        xs[c * 256 + tid] = xb[(size_t)c * HWSZ + tid];
    }
    __syncthreads();

    float acc[OO];
#pragma unroll
    for (int o = 0; o < OO; o++) acc[o] = 0.0f;

#pragma unroll 8
    for (int c = 0; c < CC; c++) {
        float xv = xs[c * 256 + tid];
        const float4* w4 = reinterpret_cast<const float4*>(ws + c * 64);
#pragma unroll
        for (int o4 = 0; o4 < 16; o4++) {
            float4 w = w4[o4];
            acc[o4 * 4 + 0] = fmaf(xv, w.x, acc[o4 * 4 + 0]);
            acc[o4 * 4 + 1] = fmaf(xv, w.y, acc[o4 * 4 + 1]);
            acc[o4 * 4 + 2] = fmaf(xv, w.z, acc[o4 * 4 + 2]);
            acc[o4 * 4 + 3] = fmaf(xv, w.w, acc[o4 * 4 + 3]);
        }
    }

    float* zb = z + (size_t)b * OO * HWSZ + base + tid;
#pragma unroll
    for (int o = 0; o < OO; o++) zb[(size_t)o * HWSZ] = acc[o];
}

// ---------------------------------------------------------------------------
// K2: out = mask ? peri_conv(z) : z
//   div[p] = sum_{c,k} (x[c, p+dk] - x[c,p])^2  (k over full 3x3, center term=0)
//   mask   = sigmoid((div - thr) * scale) > 0.5
//   conv[o,p] = sum_{j=0..7} peri[j] * z[o, p + dkj]   (8 peripheral taps)
// Grid: (8, 8, 8) = (x-tiles, y-tiles, batch). Block: 256 threads, one output
// position each (16x16 tile). Smem: x halo tile [64][324] + z halo tile
// [64][324] = 162 KB.
// ---------------------------------------------------------------------------
__global__ void spconv_post_kernel(const float* __restrict__ x,
                                   const float* __restrict__ z,
                                   const float* __restrict__ periphery,
                                   const float* __restrict__ threshold,
                                   const float* __restrict__ scale,
                                   float* __restrict__ out) {
    extern __shared__ float smem[];
    float* xs = smem;                 // [c][324] halo tile of x
    float* zs = smem + 64 * 324;      // [o][324] halo tile of z

    const int tid = threadIdx.x;
    const int tx  = tid & 15;
    const int ty  = tid >> 4;
    const int bx0 = blockIdx.x * 16;
    const int by0 = blockIdx.y * 16;
    const int b   = blockIdx.z;

    // --- cooperative halo load (zero padded) for x and z ---
    const float* xbase = x + (size_t)b * CC * HWSZ;
    const float* zbase = z + (size_t)b * OO * HWSZ;
    for (int i = tid; i < 64 * 324; i += 256) {
        int c  = i / 324;
        int p  = i - c * 324;
        int iy = p / 18;
        int ix = p - iy * 18;
        int gy = by0 + iy - 1;
        int gx = bx0 + ix - 1;
        bool inb = (gy >= 0) && (gy < HH) && (gx >= 0) && (gx < WW);
        size_t goff = (size_t)gy * WW + gx;
        xs[i] = inb ? xbase[(size_t)c * HWSZ + goff] : 0.0f;
        zs[i] = inb ? zbase[(size_t)c * HWSZ + goff] : 0.0f;
    }
    __syncthreads();

    const int p0 = (ty + 1) * 18 + (tx + 1);

    // --- div over all channels, 3x3 neighborhood ---
    float div = 0.0f;
#pragma unroll 4
    for (int c = 0; c < CC; c++) {
        const float* xc = xs + c * 324;
        float cen = xc[p0];
        float d;
        d = xc[p0 - 19] - cen; div = fmaf(d, d, div);
        d = xc[p0 - 18] - cen; div = fmaf(d, d, div);
        d = xc[p0 - 17] - cen; div = fmaf(d, d, div);
        d = xc[p0 -  1] - cen; div = fmaf(d, d, div);
        d = xc[p0 +  1] - cen; div = fmaf(d, d, div);
        d = xc[p0 + 17] - cen; div = fmaf(d, d, div);
        d = xc[p0 + 18] - cen; div = fmaf(d, d, div);
        d = xc[p0 + 19] - cen; div = fmaf(d, d, div);
    }

    const float thr = threshold[0];
    const float scl = scale[0];
    // sigmoid(t) > 0.5  <=>  t > 0 when computed exactly; keep the sigmoid
    // form to match reference semantics for any sign of scale.
    float t  = (div - thr) * scl;
    float sg = 1.0f / (1.0f + expf(-t));
    bool  m  = sg > 0.5f;

    const float pr0 = periphery[0], pr1 = periphery[1], pr2 = periphery[2],
                pr3 = periphery[3], pr4 = periphery[4], pr5 = periphery[5],
                pr6 = periphery[6], pr7 = periphery[7];

    float* ob = out + (size_t)b * OO * HWSZ + (size_t)(by0 + ty) * WW + (bx0 + tx);

#pragma unroll 4
    for (int o = 0; o < OO; o++) {
        const float* zo = zs + o * 324;
        float cen = zo[p0];
        float acc;
        acc = pr0 * zo[p0 - 19];
        acc = fmaf(pr1, zo[p0 - 18], acc);
        acc = fmaf(pr2, zo[p0 - 17], acc);
        acc = fmaf(pr3, zo[p0 -  1], acc);
        acc = fmaf(pr4, zo[p0 +  1], acc);
        acc = fmaf(pr5, zo[p0 + 17], acc);
        acc = fmaf(pr6, zo[p0 + 18], acc);
        acc = fmaf(pr7, zo[p0 + 19], acc);
        ob[(size_t)o * HWSZ] = m ? acc : cen;
    }
}

extern "C" void kernel_launch(void* const* d_in, const int* in_sizes, int n_in,
                              void* d_out, int out_size) {
    const float* x    = (const float*)d_in[0];
    const float* core = (const float*)d_in[1];
    const float* peri = (const float*)d_in[2];
    const float* thr  = (const float*)d_in[3];
    const float* scl  = (const float*)d_in[4];
    float* out = (float*)d_out;

    float* z;
    cudaGetSymbolAddress((void**)&z, g_z);

    const int smem1 = (4096 + 64 * 256) * sizeof(float);      // 80 KB
    const int smem2 = (2 * 64 * 324) * sizeof(float);         // 162 KB
    cudaFuncSetAttribute(spconv_gemm_kernel,
                         cudaFuncAttributeMaxDynamicSharedMemorySize, smem1);
    cudaFuncSetAttribute(spconv_post_kernel,
                         cudaFuncAttributeMaxDynamicSharedMemorySize, smem2);

    dim3 g1(HWSZ / 256, BB);
    spconv_gemm_kernel<<<g1, 256, smem1>>>(x, core, z);

    dim3 g2(WW / 16, HH / 16, BB);
    spconv_post_kernel<<<g2, 256, smem2>>>(x, z, peri, thr, scl, out);
}

// round 3
// speedup vs baseline: 1.8263x; 1.8263x over previous
#include <cuda_runtime.h>
#include <math.h>

#define BB 8
#define CC 64
#define OO 64
#define HH 128
#define WW 128
#define HWSZ (HH * WW)

#define TILE 16
#define HALO 18
#define NPOS (HALO * HALO)   // 324
#define NTHR 384

// ---------------------------------------------------------------------------
// Fully fused: per CTA (16x16 output tile, all 64 channels):
//   1) stage x halo [64][18*18] + W^T [64][64] in smem
//   2) per-thread: div/mask (interior 256 threads), GEMM z(p) = W^T x(p)
//      into 64 registers (324 threads, one halo position each)
//   3) reuse x smem region as z halo tile
//   4) 8-tap periphery conv over z + masked select, write out
// smem = 4096 + 20736 floats = 99,328 B
// ---------------------------------------------------------------------------
__global__ __launch_bounds__(NTHR, 1)
void spconv_fused_kernel(const float* __restrict__ x,
                         const float* __restrict__ core,
                         const float* __restrict__ periphery,
                         const float* __restrict__ threshold,
                         const float* __restrict__ scale,
                         float* __restrict__ out) {
    extern __shared__ float smem[];
    float* ws = smem;            // [c][o] = core[o][c], 4096 floats
    float* xs = smem + 4096;     // [c][324] x halo; later reused as z halo [o][324]

    const int tid = threadIdx.x;
    const int b   = blockIdx.z;
    const int bx0 = blockIdx.x * TILE;
    const int by0 = blockIdx.y * TILE;

    // --- stage W transposed ---
    for (int i = tid; i < OO * CC; i += NTHR) {
        int o = i >> 6, c = i & 63;
        ws[c * 64 + o] = core[i];
    }

    // --- stage x halo tile (zero padded) ---
    const float* xb = x + (size_t)b * CC * HWSZ;
    for (int i = tid; i < CC * NPOS; i += NTHR) {   // 54 iters exactly
        int c  = i / NPOS;
        int p  = i - c * NPOS;
        int iy = p / HALO;
        int ix = p - iy * HALO;
        int gy = by0 + iy - 1;
        int gx = bx0 + ix - 1;
        bool inb = ((unsigned)gy < HH) && ((unsigned)gx < WW);
        xs[i] = inb ? xb[(size_t)c * HWSZ + gy * WW + gx] : 0.0f;
    }
    __syncthreads();

    // --- div + mask for interior positions (threads 0..255) ---
    bool m = false;
    int p0 = 0;
    if (tid < TILE * TILE) {
        const int tx = tid & 15;
        const int ty = tid >> 4;
        p0 = (ty + 1) * HALO + (tx + 1);
        float div = 0.0f;
#pragma unroll 4
        for (int c = 0; c < CC; c++) {
            const float* xc = xs + c * NPOS;
            float cen = xc[p0];
            float d;
            d = xc[p0 - HALO - 1] - cen; div = fmaf(d, d, div);
            d = xc[p0 - HALO    ] - cen; div = fmaf(d, d, div);
            d = xc[p0 - HALO + 1] - cen; div = fmaf(d, d, div);
            d = xc[p0 - 1       ] - cen; div = fmaf(d, d, div);
            d = xc[p0 + 1       ] - cen; div = fmaf(d, d, div);
            d = xc[p0 + HALO - 1] - cen; div = fmaf(d, d, div);
            d = xc[p0 + HALO    ] - cen; div = fmaf(d, d, div);
            d = xc[p0 + HALO + 1] - cen; div = fmaf(d, d, div);
        }
        float t  = (div - threshold[0]) * scale[0];
        float sg = 1.0f / (1.0f + expf(-t));
        m = sg > 0.5f;
    }

    // --- GEMM: each thread owns one halo position, all 64 output channels ---
    float acc[OO];
#pragma unroll
    for (int o = 0; o < OO; o++) acc[o] = 0.0f;

    const int p = tid;
    if (p < NPOS) {
#pragma unroll 4
        for (int c = 0; c < CC; c++) {
            float xv = xs[c * NPOS + p];
            const float4* w4 = reinterpret_cast<const float4*>(ws + c * 64);
#pragma unroll
            for (int o4 = 0; o4 < 16; o4++) {
                float4 w = w4[o4];
                acc[o4 * 4 + 0] = fmaf(xv, w.x, acc[o4 * 4 + 0]);
                acc[o4 * 4 + 1] = fmaf(xv, w.y, acc[o4 * 4 + 1]);
                acc[o4 * 4 + 2] = fmaf(xv, w.z, acc[o4 * 4 + 2]);
                acc[o4 * 4 + 3] = fmaf(xv, w.w, acc[o4 * 4 + 3]);
            }
        }
    }
    __syncthreads();   // all xs reads done

    // --- write z halo tile into the xs region (reuse) ---
    if (p < NPOS) {
#pragma unroll
        for (int o = 0; o < OO; o++) xs[o * NPOS + p] = acc[o];
    }
    __syncthreads();

    // --- periphery conv + masked select ---
    if (tid < TILE * TILE) {
        const float pr0 = periphery[0], pr1 = periphery[1], pr2 = periphery[2],
                    pr3 = periphery[3], pr4 = periphery[4], pr5 = periphery[5],
                    pr6 = periphery[6], pr7 = periphery[7];
        const int tx = tid & 15;
        const int ty = tid >> 4;
        float* ob = out + (size_t)b * OO * HWSZ
                        + (size_t)(by0 + ty) * WW + (bx0 + tx);
#pragma unroll 4
        for (int o = 0; o < OO; o++) {
            const float* zo = xs + o * NPOS;
            float cen = zo[p0];
            float a;
            a = pr0 * zo[p0 - HALO - 1];
            a = fmaf(pr1, zo[p0 - HALO    ], a);
            a = fmaf(pr2, zo[p0 - HALO + 1], a);
            a = fmaf(pr3, zo[p0 - 1       ], a);
            a = fmaf(pr4, zo[p0 + 1       ], a);
            a = fmaf(pr5, zo[p0 + HALO - 1], a);
            a = fmaf(pr6, zo[p0 + HALO    ], a);
            a = fmaf(pr7, zo[p0 + HALO + 1], a);
            __stcg(&ob[(size_t)o * HWSZ], m ? a : cen);
        }
    }
}

extern "C" void kernel_launch(void* const* d_in, const int* in_sizes, int n_in,
                              void* d_out, int out_size) {
    const float* x    = (const float*)d_in[0];
    const float* core = (const float*)d_in[1];
    const float* peri = (const float*)d_in[2];
    const float* thr  = (const float*)d_in[3];
    const float* scl  = (const float*)d_in[4];
    float* out = (float*)d_out;

    const int smem = (4096 + CC * NPOS) * sizeof(float);  // 99,328 B
    cudaFuncSetAttribute(spconv_fused_kernel,
                         cudaFuncAttributeMaxDynamicSharedMemorySize, smem);

    dim3 grid(WW / TILE, HH / TILE, BB);   // (8, 8, 8) = 512 CTAs
    spconv_fused_kernel<<<grid, NTHR, smem>>>(x, core, peri, thr, scl, out);
}

// round 4
// speedup vs baseline: 2.0839x; 1.1411x over previous
#include <cuda_runtime.h>
#include <math.h>

#define BB 8
#define CC 64
#define OO 64
#define HH 128
#define WW 128
#define HWSZ (HH * WW)

#define TILE 16
#define HALO 18
#define NPOS (HALO * HALO)    // 324
#define NTHR 672              // 21 warps
#define NSLOT 648             // 162 pos-pairs * 4 o-quarters

// smem layout (floats):
//   ws   [0, 4096)            W^T  [c][o]
//   xs   [4096, 4096+20736)   x halo [c][324], later reused as z halo [o][324]
//   dsum [24832, 25344)       512 div partials
//   msk  [25344, 25600)       256 mask flags
#define WS_OFF   0
#define XS_OFF   4096
#define DS_OFF   (XS_OFF + CC * NPOS)
#define MK_OFF   (DS_OFF + 512)
#define SMEM_FLOATS (MK_OFF + 256)

__global__ __launch_bounds__(NTHR, 1)
void spconv_fused_kernel(const float* __restrict__ x,
                         const float* __restrict__ core,
                         const float* __restrict__ periphery,
                         const float* __restrict__ threshold,
                         const float* __restrict__ scale,
                         float* __restrict__ out) {
    extern __shared__ float smem[];
    float* ws   = smem + WS_OFF;
    float* xs   = smem + XS_OFF;
    float* dsum = smem + DS_OFF;
    float* msk  = smem + MK_OFF;

    const int tid = threadIdx.x;
    const int b   = blockIdx.z;
    const int bx0 = blockIdx.x * TILE;
    const int by0 = blockIdx.y * TILE;

    // --- stage W transposed: ws[c][o] = core[o][c] ---
    for (int i = tid; i < OO * CC; i += NTHR) {
        int o = i >> 6, c = i & 63;
        ws[c * 64 + o] = core[i];
    }

    // --- stage x halo tile (zero padded) ---
    const float* xb = x + (size_t)b * CC * HWSZ;
    for (int i = tid; i < CC * NPOS; i += NTHR) {
        int c  = i / NPOS;
        int p  = i - c * NPOS;
        int iy = p / HALO;
        int ix = p - iy * HALO;
        int gy = by0 + iy - 1;
        int gx = bx0 + ix - 1;
        bool inb = ((unsigned)gy < HH) && ((unsigned)gx < WW);
        xs[i] = inb ? xb[(size_t)c * HWSZ + gy * WW + gx] : 0.0f;
    }
    __syncthreads();

    // --- div partials: 512 threads, 2 per interior position (32 c each) ---
    if (tid < 512) {
        const int p   = tid & 255;
        const int hlf = tid >> 8;
        const int tx  = p & 15;
        const int ty  = p >> 4;
        const int q0  = (ty + 1) * HALO + (tx + 1);
        float dv = 0.0f;
        const int c0 = hlf * 32;
#pragma unroll 4
        for (int c = c0; c < c0 + 32; c++) {
            const float* xc = xs + c * NPOS;
            float cen = xc[q0];
            float d;
            d = xc[q0 - HALO - 1] - cen; dv = fmaf(d, d, dv);
            d = xc[q0 - HALO    ] - cen; dv = fmaf(d, d, dv);
            d = xc[q0 - HALO + 1] - cen; dv = fmaf(d, d, dv);
            d = xc[q0 - 1       ] - cen; dv = fmaf(d, d, dv);
            d = xc[q0 + 1       ] - cen; dv = fmaf(d, d, dv);
            d = xc[q0 + HALO - 1] - cen; dv = fmaf(d, d, dv);
            d = xc[q0 + HALO    ] - cen; dv = fmaf(d, d, dv);
            d = xc[q0 + HALO + 1] - cen; dv = fmaf(d, d, dv);
        }
        dsum[tid] = dv;
    }

    // --- GEMM: slot = (o-quarter, position-pair); 32 accs/thread ---
    float acc[32];
#pragma unroll
    for (int i = 0; i < 32; i++) acc[i] = 0.0f;

    const int s  = tid;
    const int oq = s / 162;            // 0..3 for active slots
    const int pp = s - oq * 162;       // 0..161
    const bool active = (s < NSLOT);

    if (active) {
        const float* xpair = xs + 2 * pp;
        const float* wq    = ws + oq * 16;
#pragma unroll 2
        for (int c = 0; c < CC; c++) {
            float2 xv = *reinterpret_cast<const float2*>(xpair + c * NPOS);
            const float4* w4 = reinterpret_cast<const float4*>(wq + c * 64);
#pragma unroll
            for (int i = 0; i < 4; i++) {
                float4 w = w4[i];
                acc[i * 8 + 0] = fmaf(xv.x, w.x, acc[i * 8 + 0]);
                acc[i * 8 + 1] = fmaf(xv.y, w.x, acc[i * 8 + 1]);
                acc[i * 8 + 2] = fmaf(xv.x, w.y, acc[i * 8 + 2]);
                acc[i * 8 + 3] = fmaf(xv.y, w.y, acc[i * 8 + 3]);
                acc[i * 8 + 4] = fmaf(xv.x, w.z, acc[i * 8 + 4]);
                acc[i * 8 + 5] = fmaf(xv.y, w.z, acc[i * 8 + 5]);
                acc[i * 8 + 6] = fmaf(xv.x, w.w, acc[i * 8 + 6]);
                acc[i * 8 + 7] = fmaf(xv.y, w.w, acc[i * 8 + 7]);
            }
        }
    }
    __syncthreads();   // all xs reads + dsum writes done

    // --- write z halo into xs region (float2 per output channel) ---
    if (active) {
        float* zp = xs + 2 * pp;
#pragma unroll
        for (int i = 0; i < 16; i++) {
            int o = oq * 16 + i;
            float2 v = make_float2(acc[i * 2 + 0], acc[i * 2 + 1]);
            *reinterpret_cast<float2*>(zp + o * NPOS) = v;
        }
    }

    // --- combine div partials -> mask ---
    if (tid < 256) {
        float dv = dsum[tid] + dsum[tid + 256];
        float t  = (dv - threshold[0]) * scale[0];
        float sg = 1.0f / (1.0f + expf(-t));
        msk[tid] = (sg > 0.5f) ? 1.0f : 0.0f;
    }
    __syncthreads();

    // --- periphery conv + masked select, all threads ---
    const float pr0 = periphery[0], pr1 = periphery[1], pr2 = periphery[2],
                pr3 = periphery[3], pr4 = periphery[4], pr5 = periphery[5],
                pr6 = periphery[6], pr7 = periphery[7];
    float* ob = out + (size_t)b * OO * HWSZ;

    for (int i = tid; i < OO * 256; i += NTHR) {
        int o  = i >> 8;
        int p  = i & 255;
        int tx = p & 15;
        int ty = p >> 4;
        int q0 = (ty + 1) * HALO + (tx + 1);
        const float* zo = xs + o * NPOS;
        float cen = zo[q0];
        float a;
        a = pr0 * zo[q0 - HALO - 1];
        a = fmaf(pr1, zo[q0 - HALO    ], a);
        a = fmaf(pr2, zo[q0 - HALO + 1], a);
        a = fmaf(pr3, zo[q0 - 1       ], a);
        a = fmaf(pr4, zo[q0 + 1       ], a);
        a = fmaf(pr5, zo[q0 + HALO - 1], a);
        a = fmaf(pr6, zo[q0 + HALO    ], a);
        a = fmaf(pr7, zo[q0 + HALO + 1], a);
        float r = (msk[p] > 0.5f) ? a : cen;
        __stcg(&ob[(size_t)o * HWSZ + (size_t)(by0 + ty) * WW + (bx0 + tx)], r);
    }
}

extern "C" void kernel_launch(void* const* d_in, const int* in_sizes, int n_in,
                              void* d_out, int out_size) {
    const float* x    = (const float*)d_in[0];
    const float* core = (const float*)d_in[1];
    const float* peri = (const float*)d_in[2];
    const float* thr  = (const float*)d_in[3];
    const float* scl  = (const float*)d_in[4];
    float* out = (float*)d_out;

    const int smem = SMEM_FLOATS * sizeof(float);   // 102,400 B
    cudaFuncSetAttribute(spconv_fused_kernel,
                         cudaFuncAttributeMaxDynamicSharedMemorySize, smem);

    dim3 grid(WW / TILE, HH / TILE, BB);   // 512 CTAs
    spconv_fused_kernel<<<grid, NTHR, smem>>>(x, core, peri, thr, scl, out);
}